// round 15
// baseline (speedup 1.0000x reference)
#include <cuda_runtime.h>
#include <cuda_fp16.h>
#include <math.h>
#include <stdint.h>

#define DIMX    2048
#define HEADS   16
#define DH      128
#define AINNER  2048      // HEADS*DH
#define FFI     8192
#define FUSEDW  18688     // AINNER + 2*DH + 2*FFI
#define QKVW    2304      // AINNER + 2*DH
#define SEQ     2048
#define NROWS   4096      // B*N

// ======================= scratch (static device) =======================
static __device__ float g_qkv[(size_t)NROWS * QKVW];     // 37.7 MB (fp32 q|k|v)
static __device__ float2 g_trig[SEQ * 64];
static __device__ __half g_h[(size_t)NROWS * DIMX];
static __device__ __half g_wf[(size_t)FUSEDW * DIMX];
static __device__ __half g_wa[(size_t)DIMX * AINNER];
static __device__ __half g_wo[(size_t)DIMX * FFI];
static __device__ __half g_at[(size_t)NROWS * AINNER];
static __device__ __half g_ff[(size_t)NROWS * FFI];
static __device__ __half g_q[(size_t)2 * HEADS * SEQ * DH];
static __device__ __half g_k[(size_t)2 * SEQ * DH];
static __device__ __half g_v[(size_t)2 * SEQ * DH];

__device__ __forceinline__ uint32_t smem_u32(const void* p) {
    uint32_t a;
    asm("{ .reg .u64 t; cvta.to.shared.u64 t, %1; cvt.u32.u64 %0, t; }" : "=r"(a) : "l"(p));
    return a;
}
__device__ __forceinline__ void ldmx4(uint32_t* r, uint32_t addr) {
    asm volatile("ldmatrix.sync.aligned.m8n8.x4.shared.b16 {%0,%1,%2,%3}, [%4];"
                 : "=r"(r[0]), "=r"(r[1]), "=r"(r[2]), "=r"(r[3]) : "r"(addr));
}
__device__ __forceinline__ void ldmx4t(uint32_t* r, uint32_t addr) {
    asm volatile("ldmatrix.sync.aligned.m8n8.x4.trans.shared.b16 {%0,%1,%2,%3}, [%4];"
                 : "=r"(r[0]), "=r"(r[1]), "=r"(r[2]), "=r"(r[3]) : "r"(addr));
}
__device__ __forceinline__ void mma_f16(float* c, const uint32_t* a, uint32_t b0, uint32_t b1) {
    asm volatile(
        "mma.sync.aligned.m16n8k16.row.col.f32.f16.f16.f32 "
        "{%0,%1,%2,%3}, {%4,%5,%6,%7}, {%8,%9}, {%0,%1,%2,%3};"
        : "+f"(c[0]), "+f"(c[1]), "+f"(c[2]), "+f"(c[3])
        : "r"(a[0]), "r"(a[1]), "r"(a[2]), "r"(a[3]), "r"(b0), "r"(b1));
}
__device__ __forceinline__ uint32_t pack_f16x2(float lo, float hi) {
    uint32_t r;
    asm("cvt.rn.f16x2.f32 %0, %1, %2;" : "=r"(r) : "f"(hi), "f"(lo));
    return r;
}
#define CP_ASYNC16(sa, ga) \
    asm volatile("cp.async.cg.shared.global [%0], [%1], 16;" :: "r"(sa), "l"(ga))
#define CP_COMMIT()  asm volatile("cp.async.commit_group;" ::: "memory")
#define CP_WAIT2()   asm volatile("cp.async.wait_group 2;" ::: "memory")

// ======================= trig table =======================
__global__ void trig_kernel() {
    int n = blockIdx.x, d = threadIdx.x;      // 2048 x 64
    double invf = pow(10000.0, -(double)d / 64.0);
    float theta = (float)((double)n * invf);
    g_trig[n * 64 + d] = make_float2((float)cos((double)theta), (float)sin((double)theta));
}

// ======================= LayerNorm -> fp16 =======================
__global__ void ln_half_kernel(const float* __restrict__ x,
                               const float* __restrict__ gamma,
                               const float* __restrict__ beta) {
    int r = blockIdx.x;
    const float* xr = x + (size_t)r * DIMX;
    float s = 0.f, s2 = 0.f;
    for (int i = threadIdx.x; i < DIMX; i += 256) {
        float v = xr[i]; s += v; s2 += v * v;
    }
    #pragma unroll
    for (int m = 16; m; m >>= 1) {
        s  += __shfl_xor_sync(0xffffffffu, s,  m);
        s2 += __shfl_xor_sync(0xffffffffu, s2, m);
    }
    __shared__ float red0[8], red1[8];
    int w = threadIdx.x >> 5, l = threadIdx.x & 31;
    if (l == 0) { red0[w] = s; red1[w] = s2; }
    __syncthreads();
    __shared__ float smu, srstd;
    if (threadIdx.x == 0) {
        float a = 0.f, b2 = 0.f;
        #pragma unroll
        for (int i = 0; i < 8; i++) { a += red0[i]; b2 += red1[i]; }
        float mu  = a / DIMX;
        float var = b2 / DIMX - mu * mu;
        smu = mu; srstd = 1.0f / sqrtf(var + 1e-5f);
    }
    __syncthreads();
    float mu = smu, rstd = srstd;
    for (int i = threadIdx.x; i < DIMX; i += 256) {
        float v = (xr[i] - mu) * rstd * gamma[i] + beta[i];
        g_h[(size_t)r * DIMX + i] = __float2half_rn(v);
    }
}

// ======================= transpose to K-major fp16, half2 stores =======================
// Tile: 32 output rows (n) x 64 k. Each warp stores 128B contiguous (32 x half2).
__global__ void transpose_half(const float* __restrict__ W, int K, int N, int remap,
                               __half* __restrict__ T) {
    __shared__ float t[64][33];
    int n0 = blockIdx.x * 32, k0 = blockIdx.y * 64;
    int tx = threadIdx.x, ty = threadIdx.y;
    int oc = n0 + tx;
    int sc = oc;
    if (remap && oc >= QKVW) {
        int lf = oc - QKVW;
        sc = QKVW + (lf >> 1) + ((lf & 1) ? FFI : 0);
    }
    for (int j = ty; j < 64; j += 8)
        t[j][tx] = W[(size_t)(k0 + j) * N + sc];
    __syncthreads();
    for (int j = ty; j < 32; j += 8) {
        __half2 v = __floats2half2_rn(t[2 * tx][j], t[2 * tx + 1][j]);
        *(__half2*)(T + (size_t)(n0 + j) * K + k0 + 2 * tx) = v;
    }
}

// ======================= mma.sync dual-phase GEMM (plain fp16, fp32 accum) =============
// Block tile 128x128, 4 warps (warp tile 64x64), BK=64,
// 3 smem buffers with prefetch depth 2, 96 KB smem -> 2 CTAs/SM.
#define BKC 64
#define MATB 16384                     // 128 rows x 128B
#define STAGE_BYTES (2 * MATB)              // 32768
#define GEMM_SMEM (3 * STAGE_BYTES)         // 98304
#define SW8(row, ch) ((uint32_t)((row) * 128 + (((ch) ^ ((row) & 7)) << 4)))

__global__ __launch_bounds__(128, 2)
void gemm_tc(const __half* __restrict__ A1, const __half* __restrict__ B1, int K1,
             const __half* __restrict__ A2, const __half* __restrict__ B2, int K2,
             float* __restrict__ C, int ldc, int mode) {
    extern __shared__ char smem[];
    uint32_t smb = smem_u32(smem);
    int tid = threadIdx.x;
    int w = tid >> 5, l = tid & 31;
    int wm = w & 1, wn = w >> 1;               // 2 x 2 warp grid, 64x64 per warp
    int m0 = blockIdx.x * 128;
    int n0 = blockIdx.y * 128;
    int S1 = K1 / BKC, S2 = K2 / BKC, S = S1 + S2;

    float acc[4][8][4];
    #pragma unroll
    for (int mf = 0; mf < 4; mf++)
        #pragma unroll
        for (int n = 0; n < 8; n++)
            #pragma unroll
            for (int j = 0; j < 4; j++) acc[mf][n][j] = 0.f;

    auto issue = [&](int s) {
        const __half *aa, *bb; int K, k0;
        if (s < S1) { aa = A1; bb = B1; K = K1; k0 = s * BKC; }
        else        { aa = A2; bb = B2; K = K2; k0 = (s - S1) * BKC; }
        uint32_t sb0 = smb + (s % 3) * STAGE_BYTES;
        #pragma unroll
        for (int t = 0; t < 16; t++) {
            int q = tid + (t << 7);            // 0..2047
            if (q < 1024) {                    // A: 128 rows x 8 ch
                int row = q >> 3, ch = q & 7;
                CP_ASYNC16(sb0 + SW8(row, ch),
                           aa + (size_t)(m0 + row) * K + k0 + ch * 8);
            } else {                           // B: 128 rows x 8 ch
                int rem = q - 1024;
                int row = rem >> 3, ch = rem & 7;
                CP_ASYNC16(sb0 + MATB + SW8(row, ch),
                           bb + (size_t)(n0 + row) * K + k0 + ch * 8);
            }
        }
        CP_COMMIT();
    };

    issue(0);
    if (S > 1) issue(1);
    for (int s = 0; s < S; ++s) {
        if (s + 2 < S) issue(s + 2);
        else CP_COMMIT();                      // empty group keeps wait count uniform
        CP_WAIT2();
        __syncthreads();

        uint32_t sA = smb + (s % 3) * STAGE_BYTES;
        uint32_t sB = sA + MATB;
        #pragma unroll
        for (int kk4 = 0; kk4 < 4; kk4++) {
            int chb = kk4 * 2;
            uint32_t aF[4][4], bF[4][4];
            #pragma unroll
            for (int mf = 0; mf < 4; mf++) {
                int row = wm * 64 + mf * 16 + ((l >> 3) & 1) * 8 + (l & 7);
                ldmx4(aF[mf], sA + SW8(row, chb + (l >> 4)));
            }
            #pragma unroll
            for (int u = 0; u < 4; u++) {
                int row = wn * 64 + u * 16 + (l >> 4) * 8 + (l & 7);
                ldmx4(bF[u], sB + SW8(row, chb + ((l >> 3) & 1)));
            }
            // 32 MMAs, all independent accumulators
            #pragma unroll
            for (int mf = 0; mf < 4; mf++)
                #pragma unroll
                for (int u = 0; u < 4; u++)
                    #pragma unroll
                    for (int h = 0; h < 2; h++)
                        mma_f16(acc[mf][u * 2 + h], aF[mf], bF[u][h * 2], bF[u][h * 2 + 1]);
        }
        __syncthreads();
    }

    if (mode == 1 && n0 >= QKVW) {
        // fused SwiGLU epilogue: even col = x_ff, odd col = gate (interleaved weights)
        #pragma unroll
        for (int mf = 0; mf < 4; mf++) {
            size_t row = (size_t)(m0 + wm * 64 + mf * 16 + (l >> 2));
            #pragma unroll
            for (int n = 0; n < 8; n++) {
                int j = ((n0 - QKVW) + wn * 64 + n * 8 + (l & 3) * 2) >> 1;
                float x0 = acc[mf][n][0], gt0 = acc[mf][n][1];
                float x1 = acc[mf][n][2], gt1 = acc[mf][n][3];
                float o0 = x0 * (gt0 / (1.f + __expf(-gt0)));
                float o1 = x1 * (gt1 / (1.f + __expf(-gt1)));
                g_ff[row * FFI + j]       = __float2half_rn(o0);
                g_ff[(row + 8) * FFI + j] = __float2half_rn(o1);
            }
        }
    } else {
        #pragma unroll
        for (int mf = 0; mf < 4; mf++) {
            int row = m0 + wm * 64 + mf * 16 + (l >> 2);
            #pragma unroll
            for (int n = 0; n < 8; n++) {
                int col = n0 + wn * 64 + n * 8 + (l & 3) * 2;
                *(float2*)(C + (size_t)row * ldc + col)       = make_float2(acc[mf][n][0], acc[mf][n][1]);
                *(float2*)(C + (size_t)(row + 8) * ldc + col) = make_float2(acc[mf][n][2], acc[mf][n][3]);
            }
        }
    }
}

// ======================= rope + convert (table-driven, fp16 out) =======================
__global__ void rope_convert_kernel() {
    int r = blockIdx.x;
    int b = r >> 11;
    int n = r & (SEQ - 1);
    const float* row = g_qkv + (size_t)r * QKVW;
    const float2* tab = g_trig + n * 64;
    for (int idx = threadIdx.x; idx < 1152; idx += 256) {
        if (idx < 1024) {            // q: 16 heads x 64 pairs
            int head = idx >> 6, d = idx & 63;
            float2 cs = tab[d];
            float t0 = row[head * DH + d], t1 = row[head * DH + d + 64];
            size_t base = ((size_t)(b * HEADS + head) * SEQ + n) * DH;
            g_q[base + d]      = __float2half_rn(t0 * cs.x - t1 * cs.y);
            g_q[base + d + 64] = __float2half_rn(t1 * cs.x + t0 * cs.y);
        } else if (idx < 1088) {     // k
            int d = idx - 1024;
            float2 cs = tab[d];
            float t0 = row[AINNER + d], t1 = row[AINNER + d + 64];
            size_t base = ((size_t)b * SEQ + n) * DH;
            g_k[base + d]      = __float2half_rn(t0 * cs.x - t1 * cs.y);
            g_k[base + d + 64] = __float2half_rn(t1 * cs.x + t0 * cs.y);
        } else {                     // v
            int d = idx - 1088;
            float t0 = row[AINNER + DH + d], t1 = row[AINNER + DH + d + 64];
            size_t base = ((size_t)b * SEQ + n) * DH;
            g_v[base + d]      = __float2half_rn(t0);
            g_v[base + d + 64] = __float2half_rn(t1);
        }
    }
}

// ======================= tensor-core flash attention (plain fp16) ======================
// 64-query tile, 4 warps (16 q rows each), 3-stage KV ring (depth-2 prefetch),
// 112 KB smem -> 2 CTAs/SM.
#define SW16(row, ch) ((uint32_t)((row) * 256 + (((ch) ^ ((row) & 7)) << 4)))
#define QB64 (64 * 256)                  // 16384 Q matrix
#define KB_  (64 * 256)                  // 16384 per KV matrix
#define AT_STG (2 * KB_)                 // 32768 (k, v)
#define ATTN_SMEM (QB64 + 3 * AT_STG)    // 114688

__global__ __launch_bounds__(128, 2)
void attn_mma_kernel() {
    extern __shared__ char asm_sm[];
    uint32_t smb = smem_u32(asm_sm);
    int tid = threadIdx.x, w = tid >> 5, l = tid & 31;
    int qt = gridDim.x - 1 - blockIdx.x;    // long blocks first
    int bh = blockIdx.y;
    int b = bh >> 4, h = bh & 15;

    const __half* QQ = g_q + ((size_t)bh * SEQ + qt * 64) * DH;
    const __half* KK = g_k + (size_t)b * SEQ * DH;
    const __half* VV = g_v + (size_t)b * SEQ * DH;

    auto issue_kv = [&](int jt) {
        uint32_t sb0 = smb + QB64 + (jt % 3) * AT_STG;
        int rowg = jt * 64;
        #pragma unroll
        for (int t = 0; t < 16; t++) {
            int c = tid + (t << 7);          // 0..2047
            int mat = c >> 10;               // 0 k, 1 v
            int rem = c & 1023;
            int row = rem >> 4, ch = rem & 15;
            const __half* g = mat ? VV : KK;
            CP_ASYNC16(sb0 + mat * KB_ + SW16(row, ch),
                       g + (size_t)(rowg + row) * DH + ch * 8);
        }
    };

    // Q load (16 KB) + first KV stage in group 0, second KV stage group 1
    #pragma unroll
    for (int t = 0; t < 8; t++) {
        int c = tid + (t << 7);              // 0..1023
        int row = c >> 4, ch = c & 15;
        CP_ASYNC16(smb + SW16(row, ch), QQ + (size_t)row * DH + ch * 8);
    }
    issue_kv(0);
    CP_COMMIT();
    int JT = qt;
    if (JT >= 1) issue_kv(1);
    CP_COMMIT();

    float acc_o[16][4];
    #pragma unroll
    for (int t = 0; t < 16; t++)
        #pragma unroll
        for (int j = 0; j < 4; j++) acc_o[t][j] = 0.f;
    float m_lo = -1e30f, m_hi = -1e30f, l_lo = 0.f, l_hi = 0.f;
    const float scale = 0.08838834764831845f;
    int qwbase = qt * 64 + w * 16;           // this warp's first q row

    for (int jt = 0; jt <= JT; ++jt) {
        if (jt + 2 <= JT) issue_kv(jt + 2);
        CP_COMMIT();
        CP_WAIT2();
        __syncthreads();

        uint32_t kz = smb + QB64 + (jt % 3) * AT_STG;
        uint32_t vz = kz + KB_;
        bool diag = (jt == JT);

        // ---- S = Q K^T ----
        float s[8][4];
        #pragma unroll
        for (int j = 0; j < 8; j++)
            #pragma unroll
            for (int c = 0; c < 4; c++) s[j][c] = 0.f;
        #pragma unroll
        for (int kk = 0; kk < 8; kk++) {
            int qrow = w * 16 + (l & 15);
            uint32_t aF[4];
            ldmx4(aF, smb + SW16(qrow, kk * 2 + (l >> 4)));
            #pragma unroll
            for (int j16 = 0; j16 < 4; j16++) {
                int krow = j16 * 16 + (l & 7) + ((l >= 16) ? 8 : 0);
                uint32_t bK[4];
                ldmx4(bK, kz + SW16(krow, kk * 2 + ((l >> 3) & 1)));
                mma_f16(s[2 * j16],     aF, bK[0], bK[1]);
                mma_f16(s[2 * j16 + 1], aF, bK[2], bK[3]);
            }
        }

        // ---- softmax (warp-local) ----
        int r_lo = l >> 2;
        int qg_lo = qwbase + r_lo, qg_hi = qg_lo + 8;
        float mx0 = -1e30f, mx1 = -1e30f;
        #pragma unroll
        for (int j = 0; j < 8; j++) {
            int colg = jt * 64 + j * 8 + (l & 3) * 2;
            #pragma unroll
            for (int c = 0; c < 4; c++) s[j][c] *= scale;
            if (diag) {
                if (colg     > qg_lo) s[j][0] = -1e30f;
                if (colg + 1 > qg_lo) s[j][1] = -1e30f;
                if (colg     > qg_hi) s[j][2] = -1e30f;
                if (colg + 1 > qg_hi) s[j][3] = -1e30f;
            }
            mx0 = fmaxf(mx0, fmaxf(s[j][0], s[j][1]));
            mx1 = fmaxf(mx1, fmaxf(s[j][2], s[j][3]));
        }
        mx0 = fmaxf(mx0, __shfl_xor_sync(0xffffffffu, mx0, 1));
        mx0 = fmaxf(mx0, __shfl_xor_sync(0xffffffffu, mx0, 2));
        mx1 = fmaxf(mx1, __shfl_xor_sync(0xffffffffu, mx1, 1));
        mx1 = fmaxf(mx1, __shfl_xor_sync(0xffffffffu, mx1, 2));
        float mn0 = fmaxf(m_lo, mx0), mn1 = fmaxf(m_hi, mx1);
        float al0 = __expf(m_lo - mn0), al1 = __expf(m_hi - mn1);
        float su0 = 0.f, su1 = 0.f;
        #pragma unroll
        for (int j = 0; j < 8; j++) {
            s[j][0] = __expf(s[j][0] - mn0);
            s[j][1] = __expf(s[j][1] - mn0);
            s[j][2] = __expf(s[j][2] - mn1);
            s[j][3] = __expf(s[j][3] - mn1);
            su0 += s[j][0] + s[j][1];
            su1 += s[j][2] + s[j][3];
        }
        su0 += __shfl_xor_sync(0xffffffffu, su0, 1);
        su0 += __shfl_xor_sync(0xffffffffu, su0, 2);
        su1 += __shfl_xor_sync(0xffffffffu, su1, 1);
        su1 += __shfl_xor_sync(0xffffffffu, su1, 2);
        l_lo = l_lo * al0 + su0;
        l_hi = l_hi * al1 + su1;
        m_lo = mn0; m_hi = mn1;
        #pragma unroll
        for (int t = 0; t < 16; t++) {
            acc_o[t][0] *= al0; acc_o[t][1] *= al0;
            acc_o[t][2] *= al1; acc_o[t][3] *= al1;
        }

        // ---- O += P V (P rounded to fp16) ----
        #pragma unroll
        for (int j16 = 0; j16 < 4; j16++) {
            float* t0 = s[2 * j16];
            float* t1 = s[2 * j16 + 1];
            uint32_t ph[4];
            ph[0] = pack_f16x2(t0[0], t0[1]);
            ph[1] = pack_f16x2(t0[2], t0[3]);
            ph[2] = pack_f16x2(t1[0], t1[1]);
            ph[3] = pack_f16x2(t1[2], t1[3]);
            #pragma unroll
            for (int d16 = 0; d16 < 8; d16++) {
                int vrow = j16 * 16 + (l & 7) + ((l >> 3) & 1) * 8;
                uint32_t bV[4];
                ldmx4t(bV, vz + SW16(vrow, d16 * 2 + ((l >= 16) ? 1 : 0)));
                mma_f16(acc_o[2 * d16],     ph, bV[0], bV[1]);
                mma_f16(acc_o[2 * d16 + 1], ph, bV[2], bV[3]);
            }
        }
        __syncthreads();
    }

    // ---- epilogue: normalize, write fp16 into g_at ----
    float inv0 = 1.0f / l_lo, inv1 = 1.0f / l_hi;
    size_t row0 = (size_t)(b * SEQ + qt * 64 + w * 16 + (l >> 2));
    #pragma unroll
    for (int t = 0; t < 16; t++) {
        int col = h * DH + t * 8 + (l & 3) * 2;
        g_at[row0 * AINNER + col]           = __float2half_rn(acc_o[t][0] * inv0);
        g_at[row0 * AINNER + col + 1]       = __float2half_rn(acc_o[t][1] * inv0);
        g_at[(row0 + 8) * AINNER + col]     = __float2half_rn(acc_o[t][2] * inv1);
        g_at[(row0 + 8) * AINNER + col + 1] = __float2half_rn(acc_o[t][3] * inv1);
    }
}

// ======================= launch =======================
extern "C" void kernel_launch(void* const* d_in, const int* in_sizes, int n_in,
                              void* d_out, int out_size) {
    const float* x          = (const float*)d_in[0];
    const float* gamma      = (const float*)d_in[1];
    const float* beta       = (const float*)d_in[2];
    const float* w_fused    = (const float*)d_in[3];
    const float* w_attn_out = (const float*)d_in[4];
    const float* w_ff_out   = (const float*)d_in[5];
    float* out = (float*)d_out;

    void *p;
    float *qkv;
    __half *hh, *wf, *wa, *wo, *at, *ff;
    cudaGetSymbolAddress(&p, g_qkv); qkv = (float*)p;
    cudaGetSymbolAddress(&p, g_h);   hh  = (__half*)p;
    cudaGetSymbolAddress(&p, g_wf);  wf  = (__half*)p;
    cudaGetSymbolAddress(&p, g_wa);  wa  = (__half*)p;
    cudaGetSymbolAddress(&p, g_wo);  wo  = (__half*)p;
    cudaGetSymbolAddress(&p, g_at);  at  = (__half*)p;
    cudaGetSymbolAddress(&p, g_ff);  ff  = (__half*)p;

    cudaFuncSetAttribute(gemm_tc, cudaFuncAttributeMaxDynamicSharedMemorySize, GEMM_SMEM);
    cudaFuncSetAttribute(attn_mma_kernel, cudaFuncAttributeMaxDynamicSharedMemorySize, ATTN_SMEM);

    trig_kernel<<<SEQ, 64>>>();
    // weight transpose to K-major fp16 (half2 stores); w_fused gets ff-interleave remap
    transpose_half<<<dim3(FUSEDW / 32, DIMX / 64), dim3(32, 8)>>>(w_fused, DIMX, FUSEDW, 1, wf);
    transpose_half<<<dim3(DIMX / 32, AINNER / 64), dim3(32, 8)>>>(w_attn_out, AINNER, DIMX, 0, wa);
    transpose_half<<<dim3(DIMX / 32, FFI / 64), dim3(32, 8)>>>(w_ff_out, FFI, DIMX, 0, wo);

    ln_half_kernel<<<NROWS, 256>>>(x, gamma, beta);

    // fused projection: qkv (fp32 compact) + SwiGLU'd ff (fp16) in one pass
    gemm_tc<<<dim3(NROWS / 128, FUSEDW / 128), 128, GEMM_SMEM>>>(
        hh, wf, DIMX,
        nullptr, nullptr, 0,
        qkv, QKVW, 1);

    rope_convert_kernel<<<NROWS, 256>>>();

    attn_mma_kernel<<<dim3(SEQ / 64, 2 * HEADS), 128, ATTN_SMEM>>>();

    // out = attn_out @ w_attn_out + ff @ w_ff_out (accumulated in registers)
    gemm_tc<<<dim3(NROWS / 128, DIMX / 128), 128, GEMM_SMEM>>>(
        at, wa, AINNER,
        ff, wo, FFI,
        out, DIMX, 0);
}

// round 16
// speedup vs baseline: 1.4998x; 1.4998x over previous
#include <cuda_runtime.h>
#include <cuda_fp16.h>
#include <math.h>
#include <stdint.h>

#define DIMX    2048
#define HEADS   16
#define DH      128
#define AINNER  2048      // HEADS*DH
#define FFI     8192
#define FUSEDW  18688     // AINNER + 2*DH + 2*FFI
#define QKVW    2304      // AINNER + 2*DH
#define SEQ     2048
#define NROWS   4096      // B*N

// ======================= scratch (static device) =======================
static __device__ float g_qkv[(size_t)NROWS * QKVW];     // 37.7 MB (fp32 q|k|v)
static __device__ float2 g_trig[SEQ * 64];
static __device__ __half g_h[(size_t)NROWS * DIMX];
static __device__ __half g_wf[(size_t)FUSEDW * DIMX];
static __device__ __half g_wa[(size_t)DIMX * AINNER];
static __device__ __half g_wo[(size_t)DIMX * FFI];
static __device__ __half g_at[(size_t)NROWS * AINNER];
static __device__ __half g_ff[(size_t)NROWS * FFI];
static __device__ __half g_q[(size_t)2 * HEADS * SEQ * DH];
static __device__ __half g_k[(size_t)2 * SEQ * DH];
static __device__ __half g_v[(size_t)2 * SEQ * DH];

__device__ __forceinline__ uint32_t smem_u32(const void* p) {
    uint32_t a;
    asm("{ .reg .u64 t; cvta.to.shared.u64 t, %1; cvt.u32.u64 %0, t; }" : "=r"(a) : "l"(p));
    return a;
}
__device__ __forceinline__ void ldmx4(uint32_t* r, uint32_t addr) {
    asm volatile("ldmatrix.sync.aligned.m8n8.x4.shared.b16 {%0,%1,%2,%3}, [%4];"
                 : "=r"(r[0]), "=r"(r[1]), "=r"(r[2]), "=r"(r[3]) : "r"(addr));
}
__device__ __forceinline__ void ldmx4t(uint32_t* r, uint32_t addr) {
    asm volatile("ldmatrix.sync.aligned.m8n8.x4.trans.shared.b16 {%0,%1,%2,%3}, [%4];"
                 : "=r"(r[0]), "=r"(r[1]), "=r"(r[2]), "=r"(r[3]) : "r"(addr));
}
__device__ __forceinline__ void mma_f16(float* c, const uint32_t* a, uint32_t b0, uint32_t b1) {
    asm volatile(
        "mma.sync.aligned.m16n8k16.row.col.f32.f16.f16.f32 "
        "{%0,%1,%2,%3}, {%4,%5,%6,%7}, {%8,%9}, {%0,%1,%2,%3};"
        : "+f"(c[0]), "+f"(c[1]), "+f"(c[2]), "+f"(c[3])
        : "r"(a[0]), "r"(a[1]), "r"(a[2]), "r"(a[3]), "r"(b0), "r"(b1));
}
__device__ __forceinline__ uint32_t pack_f16x2(float lo, float hi) {
    uint32_t r;
    asm("cvt.rn.f16x2.f32 %0, %1, %2;" : "=r"(r) : "f"(hi), "f"(lo));
    return r;
}
#define CP_ASYNC16(sa, ga) \
    asm volatile("cp.async.cg.shared.global [%0], [%1], 16;" :: "r"(sa), "l"(ga))
#define CP_COMMIT()  asm volatile("cp.async.commit_group;" ::: "memory")
#define CP_WAIT2()   asm volatile("cp.async.wait_group 2;" ::: "memory")

// ======================= trig table =======================
__global__ void trig_kernel() {
    int n = blockIdx.x, d = threadIdx.x;      // 2048 x 64
    double invf = pow(10000.0, -(double)d / 64.0);
    float theta = (float)((double)n * invf);
    g_trig[n * 64 + d] = make_float2((float)cos((double)theta), (float)sin((double)theta));
}

// ======================= LayerNorm -> fp16 =======================
__global__ void ln_half_kernel(const float* __restrict__ x,
                               const float* __restrict__ gamma,
                               const float* __restrict__ beta) {
    int r = blockIdx.x;
    const float* xr = x + (size_t)r * DIMX;
    float s = 0.f, s2 = 0.f;
    for (int i = threadIdx.x; i < DIMX; i += 256) {
        float v = xr[i]; s += v; s2 += v * v;
    }
    #pragma unroll
    for (int m = 16; m; m >>= 1) {
        s  += __shfl_xor_sync(0xffffffffu, s,  m);
        s2 += __shfl_xor_sync(0xffffffffu, s2, m);
    }
    __shared__ float red0[8], red1[8];
    int w = threadIdx.x >> 5, l = threadIdx.x & 31;
    if (l == 0) { red0[w] = s; red1[w] = s2; }
    __syncthreads();
    __shared__ float smu, srstd;
    if (threadIdx.x == 0) {
        float a = 0.f, b2 = 0.f;
        #pragma unroll
        for (int i = 0; i < 8; i++) { a += red0[i]; b2 += red1[i]; }
        float mu  = a / DIMX;
        float var = b2 / DIMX - mu * mu;
        smu = mu; srstd = 1.0f / sqrtf(var + 1e-5f);
    }
    __syncthreads();
    float mu = smu, rstd = srstd;
    for (int i = threadIdx.x; i < DIMX; i += 256) {
        float v = (xr[i] - mu) * rstd * gamma[i] + beta[i];
        g_h[(size_t)r * DIMX + i] = __float2half_rn(v);
    }
}

// ======================= transpose to K-major fp16, half2 stores =======================
// Tile: 32 output rows (n) x 64 k. Each warp stores 128B contiguous (32 x half2).
__global__ void transpose_half(const float* __restrict__ W, int K, int N, int remap,
                               __half* __restrict__ T) {
    __shared__ float t[64][33];
    int n0 = blockIdx.x * 32, k0 = blockIdx.y * 64;
    int tx = threadIdx.x, ty = threadIdx.y;
    int oc = n0 + tx;
    int sc = oc;
    if (remap && oc >= QKVW) {
        int lf = oc - QKVW;
        sc = QKVW + (lf >> 1) + ((lf & 1) ? FFI : 0);
    }
    for (int j = ty; j < 64; j += 8)
        t[j][tx] = W[(size_t)(k0 + j) * N + sc];
    __syncthreads();
    for (int j = ty; j < 32; j += 8) {
        __half2 v = __floats2half2_rn(t[2 * tx][j], t[2 * tx + 1][j]);
        *(__half2*)(T + (size_t)(n0 + j) * K + k0 + 2 * tx) = v;
    }
}

// ======================= mma.sync dual-phase GEMM (plain fp16, fp32 accum) =============
// Block tile 128x128, 4 warps (warp tile 64x64), BK=64,
// 3 smem buffers with prefetch depth 2, 96 KB smem -> 2 CTAs/SM.
#define BKC 64
#define MATB 16384                     // 128 rows x 128B
#define STAGE_BYTES (2 * MATB)              // 32768
#define GEMM_SMEM (3 * STAGE_BYTES)         // 98304
#define SW8(row, ch) ((uint32_t)((row) * 128 + (((ch) ^ ((row) & 7)) << 4)))

__global__ __launch_bounds__(128, 2)
void gemm_tc(const __half* __restrict__ A1, const __half* __restrict__ B1, int K1,
             const __half* __restrict__ A2, const __half* __restrict__ B2, int K2,
             float* __restrict__ C, int ldc, int mode) {
    extern __shared__ char smem[];
    uint32_t smb = smem_u32(smem);
    int tid = threadIdx.x;
    int w = tid >> 5, l = tid & 31;
    int wm = w & 1, wn = w >> 1;               // 2 x 2 warp grid, 64x64 per warp
    int m0 = blockIdx.x * 128;
    int n0 = blockIdx.y * 128;
    int S1 = K1 / BKC, S2 = K2 / BKC, S = S1 + S2;

    float acc[4][8][4];
    #pragma unroll
    for (int mf = 0; mf < 4; mf++)
        #pragma unroll
        for (int n = 0; n < 8; n++)
            #pragma unroll
            for (int j = 0; j < 4; j++) acc[mf][n][j] = 0.f;

    auto issue = [&](int s) {
        const __half *aa, *bb; int K, k0;
        if (s < S1) { aa = A1; bb = B1; K = K1; k0 = s * BKC; }
        else        { aa = A2; bb = B2; K = K2; k0 = (s - S1) * BKC; }
        uint32_t sb0 = smb + (s % 3) * STAGE_BYTES;
        #pragma unroll
        for (int t = 0; t < 16; t++) {
            int q = tid + (t << 7);            // 0..2047
            if (q < 1024) {                    // A: 128 rows x 8 ch
                int row = q >> 3, ch = q & 7;
                CP_ASYNC16(sb0 + SW8(row, ch),
                           aa + (size_t)(m0 + row) * K + k0 + ch * 8);
            } else {                           // B: 128 rows x 8 ch
                int rem = q - 1024;
                int row = rem >> 3, ch = rem & 7;
                CP_ASYNC16(sb0 + MATB + SW8(row, ch),
                           bb + (size_t)(n0 + row) * K + k0 + ch * 8);
            }
        }
        CP_COMMIT();
    };

    issue(0);
    if (S > 1) issue(1);
    for (int s = 0; s < S; ++s) {
        if (s + 2 < S) issue(s + 2);
        else CP_COMMIT();                      // empty group keeps wait count uniform
        CP_WAIT2();
        __syncthreads();

        uint32_t sA = smb + (s % 3) * STAGE_BYTES;
        uint32_t sB = sA + MATB;
        #pragma unroll
        for (int kk4 = 0; kk4 < 4; kk4++) {
            int chb = kk4 * 2;
            uint32_t aF[4][4], bF[4][4];
            #pragma unroll
            for (int mf = 0; mf < 4; mf++) {
                int row = wm * 64 + mf * 16 + ((l >> 3) & 1) * 8 + (l & 7);
                ldmx4(aF[mf], sA + SW8(row, chb + (l >> 4)));
            }
            #pragma unroll
            for (int u = 0; u < 4; u++) {
                int row = wn * 64 + u * 16 + (l >> 4) * 8 + (l & 7);
                ldmx4(bF[u], sB + SW8(row, chb + ((l >> 3) & 1)));
            }
            // 32 MMAs, all independent accumulators
            #pragma unroll
            for (int mf = 0; mf < 4; mf++)
                #pragma unroll
                for (int u = 0; u < 4; u++)
                    #pragma unroll
                    for (int h = 0; h < 2; h++)
                        mma_f16(acc[mf][u * 2 + h], aF[mf], bF[u][h * 2], bF[u][h * 2 + 1]);
        }
        __syncthreads();
    }

    if (mode == 1 && n0 >= QKVW) {
        // fused SwiGLU epilogue: even col = x_ff, odd col = gate (interleaved weights)
        #pragma unroll
        for (int mf = 0; mf < 4; mf++) {
            size_t row = (size_t)(m0 + wm * 64 + mf * 16 + (l >> 2));
            #pragma unroll
            for (int n = 0; n < 8; n++) {
                int j = ((n0 - QKVW) + wn * 64 + n * 8 + (l & 3) * 2) >> 1;
                float x0 = acc[mf][n][0], gt0 = acc[mf][n][1];
                float x1 = acc[mf][n][2], gt1 = acc[mf][n][3];
                float o0 = x0 * (gt0 / (1.f + __expf(-gt0)));
                float o1 = x1 * (gt1 / (1.f + __expf(-gt1)));
                g_ff[row * FFI + j]       = __float2half_rn(o0);
                g_ff[(row + 8) * FFI + j] = __float2half_rn(o1);
            }
        }
    } else {
        #pragma unroll
        for (int mf = 0; mf < 4; mf++) {
            int row = m0 + wm * 64 + mf * 16 + (l >> 2);
            #pragma unroll
            for (int n = 0; n < 8; n++) {
                int col = n0 + wn * 64 + n * 8 + (l & 3) * 2;
                *(float2*)(C + (size_t)row * ldc + col)       = make_float2(acc[mf][n][0], acc[mf][n][1]);
                *(float2*)(C + (size_t)(row + 8) * ldc + col) = make_float2(acc[mf][n][2], acc[mf][n][3]);
            }
        }
    }
}

// ======================= rope + convert (table-driven, fp16 out) =======================
__global__ void rope_convert_kernel() {
    int r = blockIdx.x;
    int b = r >> 11;
    int n = r & (SEQ - 1);
    const float* row = g_qkv + (size_t)r * QKVW;
    const float2* tab = g_trig + n * 64;
    for (int idx = threadIdx.x; idx < 1152; idx += 256) {
        if (idx < 1024) {            // q: 16 heads x 64 pairs
            int head = idx >> 6, d = idx & 63;
            float2 cs = tab[d];
            float t0 = row[head * DH + d], t1 = row[head * DH + d + 64];
            size_t base = ((size_t)(b * HEADS + head) * SEQ + n) * DH;
            g_q[base + d]      = __float2half_rn(t0 * cs.x - t1 * cs.y);
            g_q[base + d + 64] = __float2half_rn(t1 * cs.x + t0 * cs.y);
        } else if (idx < 1088) {     // k
            int d = idx - 1024;
            float2 cs = tab[d];
            float t0 = row[AINNER + d], t1 = row[AINNER + d + 64];
            size_t base = ((size_t)b * SEQ + n) * DH;
            g_k[base + d]      = __float2half_rn(t0 * cs.x - t1 * cs.y);
            g_k[base + d + 64] = __float2half_rn(t1 * cs.x + t0 * cs.y);
        } else {                     // v
            int d = idx - 1088;
            float t0 = row[AINNER + DH + d], t1 = row[AINNER + DH + d + 64];
            size_t base = ((size_t)b * SEQ + n) * DH;
            g_v[base + d]      = __float2half_rn(t0);
            g_v[base + d + 64] = __float2half_rn(t1);
        }
    }
}

// ======================= tensor-core flash attention (plain fp16, 3-stage KV) ==========
#define SW16(row, ch) ((uint32_t)((row) * 256 + (((ch) ^ ((row) & 7)) << 4)))
#define QB   (128 * 256)                 // 32768 Q matrix
#define KB_  (64 * 256)                  // 16384 per KV matrix
#define AT_STG (2 * KB_)                 // 32768 (k, v)
#define ATTN_SMEM (QB + 3 * AT_STG)      // 131072

__global__ __launch_bounds__(256, 1)
void attn_mma_kernel() {
    extern __shared__ char asm_sm[];
    uint32_t smb = smem_u32(asm_sm);
    int tid = threadIdx.x, w = tid >> 5, l = tid & 31;
    int qt = gridDim.x - 1 - blockIdx.x;    // long blocks first
    int bh = blockIdx.y;
    int b = bh >> 4, h = bh & 15;

    const __half* QQ = g_q + ((size_t)bh * SEQ + qt * 128) * DH;
    const __half* KK = g_k + (size_t)b * SEQ * DH;
    const __half* VV = g_v + (size_t)b * SEQ * DH;

    auto issue_kv = [&](int jt) {
        uint32_t sb0 = smb + QB + (jt % 3) * AT_STG;
        int rowg = jt * 64;
        #pragma unroll
        for (int t = 0; t < 8; t++) {
            int c = tid + (t << 8);          // 0..2047
            int mat = c >> 10;               // 0 k, 1 v
            int rem = c & 1023;
            int row = rem >> 4, ch = rem & 15;
            const __half* g = mat ? VV : KK;
            CP_ASYNC16(sb0 + mat * KB_ + SW16(row, ch),
                       g + (size_t)(rowg + row) * DH + ch * 8);
        }
    };

    // Q load + first KV stage in group 0, second KV stage group 1
    #pragma unroll
    for (int t = 0; t < 8; t++) {
        int c = tid + (t << 8);              // 0..2047
        int row = c >> 4, ch = c & 15;
        CP_ASYNC16(smb + SW16(row, ch), QQ + (size_t)row * DH + ch * 8);
    }
    issue_kv(0);
    CP_COMMIT();
    int JT = 2 * qt + 1;
    issue_kv(1);                              // JT >= 1 always
    CP_COMMIT();

    float acc_o[16][4];
    #pragma unroll
    for (int t = 0; t < 16; t++)
        #pragma unroll
        for (int j = 0; j < 4; j++) acc_o[t][j] = 0.f;
    float m_lo = -1e30f, m_hi = -1e30f, l_lo = 0.f, l_hi = 0.f;
    const float scale = 0.08838834764831845f;
    int qwbase = qt * 128 + w * 16;          // this warp's first q row

    for (int jt = 0; jt <= JT; ++jt) {
        if (jt + 2 <= JT) issue_kv(jt + 2);
        CP_COMMIT();
        CP_WAIT2();
        __syncthreads();

        if (jt * 64 <= qwbase + 15) {        // stage relevant for this warp
            uint32_t kz = smb + QB + (jt % 3) * AT_STG;
            uint32_t vz = kz + KB_;
            bool diag = (jt * 64 + 63 > qwbase);

            // ---- S = Q K^T ----
            float s[8][4];
            #pragma unroll
            for (int j = 0; j < 8; j++)
                #pragma unroll
                for (int c = 0; c < 4; c++) s[j][c] = 0.f;
            #pragma unroll
            for (int kk = 0; kk < 8; kk++) {
                int qrow = w * 16 + (l & 15);
                uint32_t aF[4];
                ldmx4(aF, smb + SW16(qrow, kk * 2 + (l >> 4)));
                #pragma unroll
                for (int j16 = 0; j16 < 4; j16++) {
                    int krow = j16 * 16 + (l & 7) + ((l >= 16) ? 8 : 0);
                    uint32_t bK[4];
                    ldmx4(bK, kz + SW16(krow, kk * 2 + ((l >> 3) & 1)));
                    mma_f16(s[2 * j16],     aF, bK[0], bK[1]);
                    mma_f16(s[2 * j16 + 1], aF, bK[2], bK[3]);
                }
            }

            // ---- softmax (warp-local) ----
            int r_lo = l >> 2;
            int qg_lo = qwbase + r_lo, qg_hi = qg_lo + 8;
            float mx0 = -1e30f, mx1 = -1e30f;
            #pragma unroll
            for (int j = 0; j < 8; j++) {
                int colg = jt * 64 + j * 8 + (l & 3) * 2;
                #pragma unroll
                for (int c = 0; c < 4; c++) s[j][c] *= scale;
                if (diag) {
                    if (colg     > qg_lo) s[j][0] = -1e30f;
                    if (colg + 1 > qg_lo) s[j][1] = -1e30f;
                    if (colg     > qg_hi) s[j][2] = -1e30f;
                    if (colg + 1 > qg_hi) s[j][3] = -1e30f;
                }
                mx0 = fmaxf(mx0, fmaxf(s[j][0], s[j][1]));
                mx1 = fmaxf(mx1, fmaxf(s[j][2], s[j][3]));
            }
            mx0 = fmaxf(mx0, __shfl_xor_sync(0xffffffffu, mx0, 1));
            mx0 = fmaxf(mx0, __shfl_xor_sync(0xffffffffu, mx0, 2));
            mx1 = fmaxf(mx1, __shfl_xor_sync(0xffffffffu, mx1, 1));
            mx1 = fmaxf(mx1, __shfl_xor_sync(0xffffffffu, mx1, 2));
            float mn0 = fmaxf(m_lo, mx0), mn1 = fmaxf(m_hi, mx1);
            float al0 = __expf(m_lo - mn0), al1 = __expf(m_hi - mn1);
            float su0 = 0.f, su1 = 0.f;
            #pragma unroll
            for (int j = 0; j < 8; j++) {
                s[j][0] = __expf(s[j][0] - mn0);
                s[j][1] = __expf(s[j][1] - mn0);
                s[j][2] = __expf(s[j][2] - mn1);
                s[j][3] = __expf(s[j][3] - mn1);
                su0 += s[j][0] + s[j][1];
                su1 += s[j][2] + s[j][3];
            }
            su0 += __shfl_xor_sync(0xffffffffu, su0, 1);
            su0 += __shfl_xor_sync(0xffffffffu, su0, 2);
            su1 += __shfl_xor_sync(0xffffffffu, su1, 1);
            su1 += __shfl_xor_sync(0xffffffffu, su1, 2);
            l_lo = l_lo * al0 + su0;
            l_hi = l_hi * al1 + su1;
            m_lo = mn0; m_hi = mn1;
            #pragma unroll
            for (int t = 0; t < 16; t++) {
                acc_o[t][0] *= al0; acc_o[t][1] *= al0;
                acc_o[t][2] *= al1; acc_o[t][3] *= al1;
            }

            // ---- O += P V (P rounded to fp16) ----
            #pragma unroll
            for (int j16 = 0; j16 < 4; j16++) {
                float* t0 = s[2 * j16];
                float* t1 = s[2 * j16 + 1];
                uint32_t ph[4];
                ph[0] = pack_f16x2(t0[0], t0[1]);
                ph[1] = pack_f16x2(t0[2], t0[3]);
                ph[2] = pack_f16x2(t1[0], t1[1]);
                ph[3] = pack_f16x2(t1[2], t1[3]);
                #pragma unroll
                for (int d16 = 0; d16 < 8; d16++) {
                    int vrow = j16 * 16 + (l & 7) + ((l >> 3) & 1) * 8;
                    uint32_t bV[4];
                    ldmx4t(bV, vz + SW16(vrow, d16 * 2 + ((l >= 16) ? 1 : 0)));
                    mma_f16(acc_o[2 * d16],     ph, bV[0], bV[1]);
                    mma_f16(acc_o[2 * d16 + 1], ph, bV[2], bV[3]);
                }
            }
        }
        __syncthreads();
    }

    // ---- epilogue: normalize, write fp16 into g_at ----
    float inv0 = 1.0f / l_lo, inv1 = 1.0f / l_hi;
    size_t row0 = (size_t)(b * SEQ + qt * 128 + w * 16 + (l >> 2));
    #pragma unroll
    for (int t = 0; t < 16; t++) {
        int col = h * DH + t * 8 + (l & 3) * 2;
        g_at[row0 * AINNER + col]           = __float2half_rn(acc_o[t][0] * inv0);
        g_at[row0 * AINNER + col + 1]       = __float2half_rn(acc_o[t][1] * inv0);
        g_at[(row0 + 8) * AINNER + col]     = __float2half_rn(acc_o[t][2] * inv1);
        g_at[(row0 + 8) * AINNER + col + 1] = __float2half_rn(acc_o[t][3] * inv1);
    }
}

// ======================= launch =======================
extern "C" void kernel_launch(void* const* d_in, const int* in_sizes, int n_in,
                              void* d_out, int out_size) {
    const float* x          = (const float*)d_in[0];
    const float* gamma      = (const float*)d_in[1];
    const float* beta       = (const float*)d_in[2];
    const float* w_fused    = (const float*)d_in[3];
    const float* w_attn_out = (const float*)d_in[4];
    const float* w_ff_out   = (const float*)d_in[5];
    float* out = (float*)d_out;

    void *p;
    float *qkv;
    __half *hh, *wf, *wa, *wo, *at, *ff;
    cudaGetSymbolAddress(&p, g_qkv); qkv = (float*)p;
    cudaGetSymbolAddress(&p, g_h);   hh  = (__half*)p;
    cudaGetSymbolAddress(&p, g_wf);  wf  = (__half*)p;
    cudaGetSymbolAddress(&p, g_wa);  wa  = (__half*)p;
    cudaGetSymbolAddress(&p, g_wo);  wo  = (__half*)p;
    cudaGetSymbolAddress(&p, g_at);  at  = (__half*)p;
    cudaGetSymbolAddress(&p, g_ff);  ff  = (__half*)p;

    cudaFuncSetAttribute(gemm_tc, cudaFuncAttributeMaxDynamicSharedMemorySize, GEMM_SMEM);
    cudaFuncSetAttribute(attn_mma_kernel, cudaFuncAttributeMaxDynamicSharedMemorySize, ATTN_SMEM);

    trig_kernel<<<SEQ, 64>>>();
    // weight transpose to K-major fp16 (half2 stores); w_fused gets ff-interleave remap
    transpose_half<<<dim3(FUSEDW / 32, DIMX / 64), dim3(32, 8)>>>(w_fused, DIMX, FUSEDW, 1, wf);
    transpose_half<<<dim3(DIMX / 32, AINNER / 64), dim3(32, 8)>>>(w_attn_out, AINNER, DIMX, 0, wa);
    transpose_half<<<dim3(DIMX / 32, FFI / 64), dim3(32, 8)>>>(w_ff_out, FFI, DIMX, 0, wo);

    ln_half_kernel<<<NROWS, 256>>>(x, gamma, beta);

    // fused projection: qkv (fp32 compact) + SwiGLU'd ff (fp16) in one pass
    gemm_tc<<<dim3(NROWS / 128, FUSEDW / 128), 128, GEMM_SMEM>>>(
        hh, wf, DIMX,
        nullptr, nullptr, 0,
        qkv, QKVW, 1);

    rope_convert_kernel<<<NROWS, 256>>>();

    attn_mma_kernel<<<dim3(SEQ / 128, 2 * HEADS), 256, ATTN_SMEM>>>();

    // out = attn_out @ w_attn_out + ff @ w_ff_out (accumulated in registers)
    gemm_tc<<<dim3(NROWS / 128, DIMX / 128), 128, GEMM_SMEM>>>(
        at, wa, AINNER,
        ff, wo, FFI,
        out, DIMX, 0);
}